// round 4
// baseline (speedup 1.0000x reference)
#include <cuda_runtime.h>
#include <math.h>

#define F_IN 128
#define HID  16
#define NC   10
#define CP   12            // C padded to 12 so scatters are v4-aligned
#define N_MAX 100000
#define E_MAX 1600000

// ---------------- scratch (allocation-free, 16B-aligned for v4 ops) ----------
__device__ __align__(16) float g_a0   [N_MAX * HID];   // x @ W1[0]
__device__ __align__(16) float g_ad   [N_MAX * HID];   // x @ (W1[1]-W1[0])
__device__ __align__(16) float g_base1[N_MAX * HID];   // x @ root1 + b1
__device__ __align__(16) float g_agg1 [N_MAX * HID];
__device__ __align__(16) float g_deg  [N_MAX];
__device__ __align__(16) float g_b0   [N_MAX * CP];    // h @ W2[0]   (cols 10,11 = 0)
__device__ __align__(16) float g_bd   [N_MAX * CP];    // h @ (W2[1]-W2[0])
__device__ __align__(16) float g_base2[N_MAX * CP];    // h @ root2 + b2
__device__ __align__(16) float g_agg2 [N_MAX * CP];

// ---------------- zero accumulators ----------------
__global__ void zero_kernel(int N) {
    int total = N * HID + N * CP + N;     // agg1 + agg2 + deg
    for (int i = blockIdx.x * blockDim.x + threadIdx.x; i < total;
         i += gridDim.x * blockDim.x) {
        if (i < N * HID)               g_agg1[i] = 0.f;
        else if (i < N * HID + N * CP) g_agg2[i - N * HID] = 0.f;
        else                           g_deg[i - N * HID - N * CP] = 0.f;
    }
}

// ---------------- layer-1 node transform ----------------
// per node: a0 = x@W0, ad = x@(W1-W0), base1 = x@root1 + b1
__global__ __launch_bounds__(128)
void node1_kernel(const float* __restrict__ x,
                  const float* __restrict__ W1,
                  const float* __restrict__ root1,
                  const float* __restrict__ b1, int N)
{
    __shared__ float sW0[F_IN * HID];
    __shared__ float sWd[F_IN * HID];
    __shared__ float sR [F_IN * HID];
    for (int i = threadIdx.x; i < F_IN * HID; i += blockDim.x) {
        float w0 = W1[i];
        sW0[i] = w0;
        sWd[i] = W1[F_IN * HID + i] - w0;
        sR [i] = root1[i];
    }
    __syncthreads();

    int n = blockIdx.x * blockDim.x + threadIdx.x;
    if (n >= N) return;

    float acc0[HID], accd[HID], accr[HID];
#pragma unroll
    for (int j = 0; j < HID; j++) { acc0[j] = 0.f; accd[j] = 0.f; accr[j] = 0.f; }

    const float4* xr = reinterpret_cast<const float4*>(x + (size_t)n * F_IN);
#pragma unroll 4
    for (int k4 = 0; k4 < F_IN / 4; k4++) {
        float4 xv = __ldg(&xr[k4]);
        float xs[4] = { xv.x, xv.y, xv.z, xv.w };
#pragma unroll
        for (int kk = 0; kk < 4; kk++) {
            float xk  = xs[kk];
            int  base = (k4 * 4 + kk) * HID;
#pragma unroll
            for (int j4 = 0; j4 < HID / 4; j4++) {
                float4 w0 = *reinterpret_cast<const float4*>(&sW0[base + j4 * 4]);
                float4 wd = *reinterpret_cast<const float4*>(&sWd[base + j4 * 4]);
                float4 wr = *reinterpret_cast<const float4*>(&sR [base + j4 * 4]);
                acc0[j4*4+0] += xk * w0.x; acc0[j4*4+1] += xk * w0.y;
                acc0[j4*4+2] += xk * w0.z; acc0[j4*4+3] += xk * w0.w;
                accd[j4*4+0] += xk * wd.x; accd[j4*4+1] += xk * wd.y;
                accd[j4*4+2] += xk * wd.z; accd[j4*4+3] += xk * wd.w;
                accr[j4*4+0] += xk * wr.x; accr[j4*4+1] += xk * wr.y;
                accr[j4*4+2] += xk * wr.z; accr[j4*4+3] += xk * wr.w;
            }
        }
    }
#pragma unroll
    for (int j4 = 0; j4 < HID / 4; j4++) {
        *reinterpret_cast<float4*>(&g_a0[(size_t)n * HID + j4 * 4]) =
            make_float4(acc0[j4*4], acc0[j4*4+1], acc0[j4*4+2], acc0[j4*4+3]);
        *reinterpret_cast<float4*>(&g_ad[(size_t)n * HID + j4 * 4]) =
            make_float4(accd[j4*4], accd[j4*4+1], accd[j4*4+2], accd[j4*4+3]);
        float4 bb = make_float4(accr[j4*4]   + b1[j4*4],
                                accr[j4*4+1] + b1[j4*4+1],
                                accr[j4*4+2] + b1[j4*4+2],
                                accr[j4*4+3] + b1[j4*4+3]);
        *reinterpret_cast<float4*>(&g_base1[(size_t)n * HID + j4 * 4]) = bb;
    }
}

// ---------------- layer-1 edge pass: 4 lanes per edge ----------------
// edge_index delivered as int32 (harness has no int64 path): [2, E] row-major.
__global__ void edge1_kernel(const int* __restrict__ ei,
                             const float* __restrict__ attr, int E)
{
    int t = blockIdx.x * blockDim.x + threadIdx.x;
    int e = t >> 2;
    int r = t & 3;
    if (e >= E) return;
    int   s = __ldg(&ei[e]);
    int   d = __ldg(&ei[E + e]);
    float w = __ldg(&attr[e]);

    float4 m0 = *reinterpret_cast<const float4*>(&g_a0[(size_t)s * HID + r * 4]);
    float4 md = *reinterpret_cast<const float4*>(&g_ad[(size_t)s * HID + r * 4]);
    float4 msg = make_float4(m0.x + w * md.x, m0.y + w * md.y,
                             m0.z + w * md.z, m0.w + w * md.w);
    float* dstp = &g_agg1[(size_t)d * HID + r * 4];
    asm volatile("red.global.add.v4.f32 [%0], {%1,%2,%3,%4};"
                 :: "l"(dstp), "f"(msg.x), "f"(msg.y), "f"(msg.z), "f"(msg.w)
                 : "memory");
    if (r == 0) atomicAdd(&g_deg[d], 1.0f);
}

// ---------------- layer-1 finalize + ELU + layer-2 node transform ------------
__global__ __launch_bounds__(128)
void node2_kernel(const float* __restrict__ W2,
                  const float* __restrict__ root2,
                  const float* __restrict__ b2, int N)
{
    __shared__ float sB0[HID * CP];
    __shared__ float sBd[HID * CP];
    __shared__ float sR [HID * CP];
    __shared__ float sb2[CP];
    for (int i = threadIdx.x; i < HID * CP; i += blockDim.x) {
        int j = i / CP, c = i - j * CP;
        float w0 = (c < NC) ? W2[j * NC + c] : 0.f;
        float w1 = (c < NC) ? W2[HID * NC + j * NC + c] : 0.f;
        sB0[i] = w0;
        sBd[i] = w1 - w0;
        sR [i] = (c < NC) ? root2[j * NC + c] : 0.f;
    }
    if (threadIdx.x < CP) sb2[threadIdx.x] = (threadIdx.x < NC) ? b2[threadIdx.x] : 0.f;
    __syncthreads();

    int n = blockIdx.x * blockDim.x + threadIdx.x;
    if (n >= N) return;

    float inv = 1.f / fmaxf(g_deg[n], 1.f);
    float h[HID];
#pragma unroll
    for (int j4 = 0; j4 < HID / 4; j4++) {
        float4 ag = *reinterpret_cast<const float4*>(&g_agg1 [(size_t)n * HID + j4 * 4]);
        float4 bs = *reinterpret_cast<const float4*>(&g_base1[(size_t)n * HID + j4 * 4]);
        float v[4] = { ag.x * inv + bs.x, ag.y * inv + bs.y,
                       ag.z * inv + bs.z, ag.w * inv + bs.w };
#pragma unroll
        for (int q = 0; q < 4; q++)
            h[j4 * 4 + q] = (v[q] > 0.f) ? v[q] : expm1f(v[q]);
    }

    float o0[CP], od[CP], orr[CP];
#pragma unroll
    for (int c = 0; c < CP; c++) { o0[c] = 0.f; od[c] = 0.f; orr[c] = 0.f; }
#pragma unroll
    for (int j = 0; j < HID; j++) {
        float hj = h[j];
#pragma unroll
        for (int c4 = 0; c4 < CP / 4; c4++) {
            float4 w0 = *reinterpret_cast<const float4*>(&sB0[j * CP + c4 * 4]);
            float4 wd = *reinterpret_cast<const float4*>(&sBd[j * CP + c4 * 4]);
            float4 wr = *reinterpret_cast<const float4*>(&sR [j * CP + c4 * 4]);
            o0[c4*4+0] += hj * w0.x; o0[c4*4+1] += hj * w0.y;
            o0[c4*4+2] += hj * w0.z; o0[c4*4+3] += hj * w0.w;
            od[c4*4+0] += hj * wd.x; od[c4*4+1] += hj * wd.y;
            od[c4*4+2] += hj * wd.z; od[c4*4+3] += hj * wd.w;
            orr[c4*4+0] += hj * wr.x; orr[c4*4+1] += hj * wr.y;
            orr[c4*4+2] += hj * wr.z; orr[c4*4+3] += hj * wr.w;
        }
    }
#pragma unroll
    for (int c4 = 0; c4 < CP / 4; c4++) {
        *reinterpret_cast<float4*>(&g_b0[(size_t)n * CP + c4 * 4]) =
            make_float4(o0[c4*4], o0[c4*4+1], o0[c4*4+2], o0[c4*4+3]);
        *reinterpret_cast<float4*>(&g_bd[(size_t)n * CP + c4 * 4]) =
            make_float4(od[c4*4], od[c4*4+1], od[c4*4+2], od[c4*4+3]);
        *reinterpret_cast<float4*>(&g_base2[(size_t)n * CP + c4 * 4]) =
            make_float4(orr[c4*4] + sb2[c4*4],   orr[c4*4+1] + sb2[c4*4+1],
                        orr[c4*4+2] + sb2[c4*4+2], orr[c4*4+3] + sb2[c4*4+3]);
    }
}

// ---------------- layer-2 edge pass: 3 lanes per edge (CP=12), 10 edges/warp --
__global__ void edge2_kernel(const int* __restrict__ ei,
                             const float* __restrict__ attr, int E)
{
    int t    = blockIdx.x * blockDim.x + threadIdx.x;
    int warp = t >> 5;
    int lane = t & 31;
    if (lane >= 30) return;
    int el = lane / 3;                // 0..9
    int r  = lane - el * 3;           // 0..2
    int e  = warp * 10 + el;
    if (e >= E) return;

    int   s = __ldg(&ei[e]);
    int   d = __ldg(&ei[E + e]);
    float w = __ldg(&attr[e]);

    float4 m0 = *reinterpret_cast<const float4*>(&g_b0[(size_t)s * CP + r * 4]);
    float4 md = *reinterpret_cast<const float4*>(&g_bd[(size_t)s * CP + r * 4]);
    float4 msg = make_float4(m0.x + w * md.x, m0.y + w * md.y,
                             m0.z + w * md.z, m0.w + w * md.w);
    float* dstp = &g_agg2[(size_t)d * CP + r * 4];
    asm volatile("red.global.add.v4.f32 [%0], {%1,%2,%3,%4};"
                 :: "l"(dstp), "f"(msg.x), "f"(msg.y), "f"(msg.z), "f"(msg.w)
                 : "memory");
}

// ---------------- output ----------------
__global__ void out_kernel(float* __restrict__ out, int N)
{
    int t = blockIdx.x * blockDim.x + threadIdx.x;
    if (t >= N * NC) return;
    int n = t / NC;
    int c = t - n * NC;
    float inv = 1.f / fmaxf(g_deg[n], 1.f);
    out[t] = g_agg2[(size_t)n * CP + c] * inv + g_base2[(size_t)n * CP + c];
}

// ---------------- launcher ----------------
extern "C" void kernel_launch(void* const* d_in, const int* in_sizes, int n_in,
                              void* d_out, int out_size)
{
    const float* x     = (const float*)d_in[0];
    const int*   ei    = (const int*)d_in[1];     // int64 in ref -> int32 on device
    const float* attr  = (const float*)d_in[2];
    const float* W1    = (const float*)d_in[3];
    const float* root1 = (const float*)d_in[4];
    const float* b1    = (const float*)d_in[5];
    const float* W2    = (const float*)d_in[6];
    const float* root2 = (const float*)d_in[7];
    const float* b2    = (const float*)d_in[8];
    float*       out   = (float*)d_out;

    int N = in_sizes[0] / F_IN;
    int E = in_sizes[2];           // edge_attr is (E,1)

    zero_kernel<<<1024, 256>>>(N);
    node1_kernel<<<(N + 127) / 128, 128>>>(x, W1, root1, b1, N);

    long long t1 = (long long)E * 4;
    edge1_kernel<<<(unsigned)((t1 + 255) / 256), 256>>>(ei, attr, E);

    node2_kernel<<<(N + 127) / 128, 128>>>(W2, root2, b2, N);

    long long nwarps = ((long long)E + 9) / 10;
    long long t2 = nwarps * 32;
    edge2_kernel<<<(unsigned)((t2 + 255) / 256), 256>>>(ei, attr, E);

    out_kernel<<<(N * NC + 255) / 256, 256>>>(out, N);
}